// round 1
// baseline (speedup 1.0000x reference)
#include <cuda_runtime.h>
#include <cuda_bf16.h>

#define HH 16
#define DD 64
#define BM 128
#define BN 32

__global__ __launch_bounds__(BM) void varlen_attn_kernel(
    const float* __restrict__ Q,
    const float* __restrict__ K,
    const float* __restrict__ V,
    const int*   __restrict__ cu_q,
    const int*   __restrict__ cu_k,
    float*       __restrict__ O,
    int B)
{
    __shared__ float ks[BN][DD];
    __shared__ float vs[BN][DD];

    const int h = blockIdx.y;

    // ---- decode linear tile index -> (batch, tile within batch) ----
    int t = blockIdx.x;
    int b = 0, q0 = 0, lenq = 0;
    for (b = 0; b < B; b++) {
        q0   = cu_q[b];
        lenq = cu_q[b + 1] - q0;
        int nt = (lenq + BM - 1) / BM;
        if (t < nt) break;
        t -= nt;
    }
    if (b >= B) return;

    const int k0   = cu_k[b];
    const int lenk = cu_k[b + 1] - k0;
    const int off  = lenk - lenq;  // flash-varlen causal alignment

    const int  qi     = t * BM + (int)threadIdx.x;   // query row within sequence
    const bool active = (qi < lenq);
    const int  q_hi   = min(t * BM + BM, lenq) - 1;  // last valid row in this tile
    const int  kmax   = min(lenk, q_hi + off + 1);   // keys any row of this tile can see
    const int  myvis  = active ? min(lenk, qi + off + 1) : 0;

    // fold softmax scale and log2(e) into q so scores are directly exp2 args
    const float SC = 0.125f * 1.4426950408889634f;   // (1/sqrt(64)) * log2(e)

    float q[DD];
    {
        const float* qp = Q + ((long)(q0 + (active ? qi : 0)) * HH + h) * DD;
        #pragma unroll
        for (int d = 0; d < DD; d += 4) {
            float4 v4 = *(const float4*)(qp + d);
            q[d + 0] = v4.x * SC;
            q[d + 1] = v4.y * SC;
            q[d + 2] = v4.z * SC;
            q[d + 3] = v4.w * SC;
        }
    }

    float acc[DD];
    #pragma unroll
    for (int d = 0; d < DD; d++) acc[d] = 0.0f;
    float m = -1e30f;
    float l = 0.0f;

    for (int kt = 0; kt < kmax; kt += BN) {
        // ---- cooperative K/V tile load: 512 float4s across 128 threads ----
        #pragma unroll
        for (int i = 0; i < 4; i++) {
            int f  = (int)threadIdx.x + i * BM;  // 0..511
            int j  = f >> 4;                     // key row in tile (16 f4 per row)
            int d4 = (f & 15) << 2;              // dim offset
            int jg = kt + j;
            float4 kv = make_float4(0.f, 0.f, 0.f, 0.f);
            float4 vv = make_float4(0.f, 0.f, 0.f, 0.f);
            if (jg < lenk) {
                long base = ((long)(k0 + jg) * HH + h) * DD + d4;
                kv = *(const float4*)(K + base);
                vv = *(const float4*)(V + base);
            }
            *(float4*)&ks[j][d4] = kv;
            *(float4*)&vs[j][d4] = vv;
        }
        __syncthreads();

        // ---- scores for this tile (registers), with causal/bounds mask ----
        float s[BN];
        float tmax = -1e30f;
        #pragma unroll
        for (int j = 0; j < BN; j++) {
            float4 a4 = make_float4(0.f, 0.f, 0.f, 0.f);
            #pragma unroll
            for (int d = 0; d < DD; d += 4) {
                float4 k4 = *(const float4*)&ks[j][d];
                a4.x += q[d + 0] * k4.x;
                a4.y += q[d + 1] * k4.y;
                a4.z += q[d + 2] * k4.z;
                a4.w += q[d + 3] * k4.w;
            }
            float sv = (a4.x + a4.y) + (a4.z + a4.w);
            int jg   = kt + j;
            bool vis = active && (jg <= qi + off) && (jg < lenk);
            s[j] = vis ? sv : -1e30f;
            tmax = fmaxf(tmax, s[j]);
        }

        const float mnew = fmaxf(m, tmax);
        const float corr = exp2f(m - mnew);
        m = mnew;

        #pragma unroll
        for (int d = 0; d < DD; d++) acc[d] *= corr;
        l *= corr;

        // ---- PV accumulate ----
        float psum = 0.0f;
        #pragma unroll
        for (int j = 0; j < BN; j++) {
            float p = exp2f(s[j] - mnew);
            psum += p;
            #pragma unroll
            for (int d = 0; d < DD; d += 4) {
                float4 v4 = *(const float4*)&vs[j][d];
                acc[d + 0] += p * v4.x;
                acc[d + 1] += p * v4.y;
                acc[d + 2] += p * v4.z;
                acc[d + 3] += p * v4.w;
            }
        }
        l += psum;

        __syncthreads();
    }

    if (active) {
        float inv = (myvis > 0 && l > 0.0f) ? (1.0f / l) : 0.0f;
        float* op = O + ((long)(q0 + qi) * HH + h) * DD;
        #pragma unroll
        for (int d = 0; d < DD; d += 4) {
            float4 o4;
            o4.x = acc[d + 0] * inv;
            o4.y = acc[d + 1] * inv;
            o4.z = acc[d + 2] * inv;
            o4.w = acc[d + 3] * inv;
            *(float4*)(op + d) = o4;
        }
    }
}

extern "C" void kernel_launch(void* const* d_in, const int* in_sizes, int n_in,
                              void* d_out, int out_size)
{
    const float* Q = (const float*)d_in[0];
    const float* K = (const float*)d_in[1];
    const float* V = (const float*)d_in[2];
    const int* cu_q = (const int*)d_in[3];
    const int* cu_k = (const int*)d_in[4];

    int B = in_sizes[3] - 1;
    int T = in_sizes[0] / (HH * DD);

    int max_tiles = (T + BM - 1) / BM + B;   // upper bound on sum of per-batch tiles
    dim3 grid(max_tiles, HH);
    varlen_attn_kernel<<<grid, BM>>>(Q, K, V, cu_q, cu_k, (float*)d_out, B);
}

// round 2
// speedup vs baseline: 6.0670x; 6.0670x over previous
#include <cuda_runtime.h>
#include <cuda_bf16.h>

#define HH 16
#define DD 64
#define BM 64
#define BN 64
#define KST 68   // padded smem row stride (floats/words)

__device__ __forceinline__ unsigned f2tf(float f) {
    unsigned r; asm("cvt.rna.tf32.f32 %0, %1;" : "=r"(r) : "f"(f)); return r;
}
__device__ __forceinline__ float ex2(float x) {
    float r; asm("ex2.approx.f32 %0, %1;" : "=f"(r) : "f"(x)); return r;
}
__device__ __forceinline__ void mma8(float* c, const unsigned* a, unsigned b0, unsigned b1) {
    asm volatile("mma.sync.aligned.m16n8k8.row.col.f32.tf32.tf32.f32 "
        "{%0,%1,%2,%3}, {%4,%5,%6,%7}, {%8,%9}, {%0,%1,%2,%3};"
        : "+f"(c[0]), "+f"(c[1]), "+f"(c[2]), "+f"(c[3])
        : "r"(a[0]), "r"(a[1]), "r"(a[2]), "r"(a[3]), "r"(b0), "r"(b1));
}

__global__ __launch_bounds__(128) void varlen_attn_mma(
    const float* __restrict__ Q,
    const float* __restrict__ K,
    const float* __restrict__ V,
    const int*   __restrict__ cu_q,
    const int*   __restrict__ cu_k,
    float*       __restrict__ O,
    int B)
{
    __shared__ unsigned ksu[BN][KST];
    __shared__ unsigned vsu[BN][KST];

    const int h = blockIdx.y;

    // ---- decode linear tile index -> (batch, tile) ----
    int t = blockIdx.x;
    int b, q0 = 0, lenq = 0;
    for (b = 0; b < B; b++) {
        q0 = cu_q[b]; lenq = cu_q[b + 1] - q0;
        int nt = (lenq + BM - 1) / BM;
        if (t < nt) break;
        t -= nt;
    }
    if (b >= B) return;
    const int k0   = cu_k[b];
    const int lenk = cu_k[b + 1] - k0;
    const int off  = lenk - lenq;

    const int tid  = threadIdx.x;
    const int warp = tid >> 5, lane = tid & 31;
    const int g    = lane >> 2, tg = lane & 3;

    const int rowbase = t * BM;
    const int qi0 = rowbase + warp * 16 + g;   // this thread's row 0
    const int qi1 = qi0 + 8;                   // row 1

    // ---- stage Q tile (fp32) through smem, build A fragments ----
    {
        float* qsf = (float*)ksu;
        #pragma unroll
        for (int i = 0; i < 8; i++) {
            int f = tid + i * 128;
            int r = f >> 4, d4 = (f & 15) << 2;
            int qr = rowbase + r;
            float4 v = make_float4(0.f, 0.f, 0.f, 0.f);
            if (qr < lenq)
                v = *(const float4*)(Q + ((long)(q0 + qr) * HH + h) * DD + d4);
            *(float4*)&qsf[r * KST + d4] = v;
        }
    }
    __syncthreads();

    const float SC = 0.125f * 1.4426950408889634f;  // 1/sqrt(64) * log2(e)
    unsigned qa[8][4];
    {
        const float* qsf = (const float*)ksu;
        const int r0 = warp * 16 + g, r1 = r0 + 8;
        #pragma unroll
        for (int k8 = 0; k8 < 8; k8++) {
            qa[k8][0] = f2tf(qsf[r0 * KST + k8 * 8 + tg]     * SC);
            qa[k8][1] = f2tf(qsf[r1 * KST + k8 * 8 + tg]     * SC);
            qa[k8][2] = f2tf(qsf[r0 * KST + k8 * 8 + tg + 4] * SC);
            qa[k8][3] = f2tf(qsf[r1 * KST + k8 * 8 + tg + 4] * SC);
        }
    }
    __syncthreads();

    float o[8][4];
    #pragma unroll
    for (int nt = 0; nt < 8; nt++)
        o[nt][0] = o[nt][1] = o[nt][2] = o[nt][3] = 0.f;
    float m0 = -1e30f, m1 = -1e30f, l0 = 0.f, l1 = 0.f;

    const int q_hi = min(rowbase + BM, lenq) - 1;
    const int kmax = min(lenk, q_hi + off + 1);

    for (int kt = 0; kt < kmax; kt += BN) {
        // ---- stage K/V tile, converting fp32 -> tf32 once ----
        #pragma unroll
        for (int i = 0; i < 8; i++) {
            int f = tid + i * 128;
            int r = f >> 4, d4 = (f & 15) << 2;
            int jg = kt + r;
            float4 kv = make_float4(0.f, 0.f, 0.f, 0.f), vv = kv;
            if (jg < lenk) {
                long base = ((long)(k0 + jg) * HH + h) * DD + d4;
                kv = *(const float4*)(K + base);
                vv = *(const float4*)(V + base);
            }
            *(uint4*)&ksu[r][d4] = make_uint4(f2tf(kv.x), f2tf(kv.y), f2tf(kv.z), f2tf(kv.w));
            *(uint4*)&vsu[r][d4] = make_uint4(f2tf(vv.x), f2tf(vv.y), f2tf(vv.z), f2tf(vv.w));
        }
        __syncthreads();

        // ---- S = Q K^T  (8 n-tiles of keys, 8 k-steps over d) ----
        float s[8][4];
        #pragma unroll
        for (int nt = 0; nt < 8; nt++)
            s[nt][0] = s[nt][1] = s[nt][2] = s[nt][3] = 0.f;
        #pragma unroll
        for (int k8 = 0; k8 < 8; k8++) {
            #pragma unroll
            for (int nt = 0; nt < 8; nt++) {
                unsigned b0 = ksu[nt * 8 + g][k8 * 8 + tg];
                unsigned b1 = ksu[nt * 8 + g][k8 * 8 + tg + 4];
                mma8(s[nt], qa[k8], b0, b1);
            }
        }

        // ---- causal mask + row max ----
        float tmax0 = -1e30f, tmax1 = -1e30f;
        #pragma unroll
        for (int nt = 0; nt < 8; nt++) {
            int j0 = kt + nt * 8 + 2 * tg, j1 = j0 + 1;
            s[nt][0] = (j0 <= qi0 + off) ? s[nt][0] : -1e30f;
            s[nt][1] = (j1 <= qi0 + off) ? s[nt][1] : -1e30f;
            s[nt][2] = (j0 <= qi1 + off) ? s[nt][2] : -1e30f;
            s[nt][3] = (j1 <= qi1 + off) ? s[nt][3] : -1e30f;
            tmax0 = fmaxf(tmax0, fmaxf(s[nt][0], s[nt][1]));
            tmax1 = fmaxf(tmax1, fmaxf(s[nt][2], s[nt][3]));
        }
        tmax0 = fmaxf(tmax0, __shfl_xor_sync(0xffffffffu, tmax0, 1));
        tmax0 = fmaxf(tmax0, __shfl_xor_sync(0xffffffffu, tmax0, 2));
        tmax1 = fmaxf(tmax1, __shfl_xor_sync(0xffffffffu, tmax1, 1));
        tmax1 = fmaxf(tmax1, __shfl_xor_sync(0xffffffffu, tmax1, 2));

        const float mn0 = fmaxf(m0, tmax0), mn1 = fmaxf(m1, tmax1);
        const float cr0 = ex2(m0 - mn0),    cr1 = ex2(m1 - mn1);
        m0 = mn0; m1 = mn1;
        l0 *= cr0; l1 *= cr1;

        // ---- p = exp2(s - m), accumulate partial row sums (quad-reduced at end) ----
        #pragma unroll
        for (int nt = 0; nt < 8; nt++) {
            float p0 = ex2(s[nt][0] - mn0);
            float p1 = ex2(s[nt][1] - mn0);
            float p2 = ex2(s[nt][2] - mn1);
            float p3 = ex2(s[nt][3] - mn1);
            l0 += p0 + p1; l1 += p2 + p3;
            s[nt][0] = p0; s[nt][1] = p1; s[nt][2] = p2; s[nt][3] = p3;
        }
        #pragma unroll
        for (int nt = 0; nt < 8; nt++) {
            o[nt][0] *= cr0; o[nt][1] *= cr0;
            o[nt][2] *= cr1; o[nt][3] *= cr1;
        }

        // ---- O += P V  (key-permuted B fragments: k-index r <-> key 2r / 2r-7) ----
        #pragma unroll
        for (int k8 = 0; k8 < 8; k8++) {
            unsigned pa[4];
            pa[0] = f2tf(s[k8][0]);   // a0: row g,   k-idx tg   -> key 8k8+2tg
            pa[1] = f2tf(s[k8][2]);   // a1: row g+8, k-idx tg
            pa[2] = f2tf(s[k8][1]);   // a2: row g,   k-idx tg+4 -> key 8k8+2tg+1
            pa[3] = f2tf(s[k8][3]);   // a3: row g+8, k-idx tg+4
            const int kr0 = k8 * 8 + 2 * tg, kr1 = kr0 + 1;
            #pragma unroll
            for (int nt = 0; nt < 8; nt++) {
                unsigned b0 = vsu[kr0][nt * 8 + g];
                unsigned b1 = vsu[kr1][nt * 8 + g];
                mma8(o[nt], pa, b0, b1);
            }
        }
        __syncthreads();
    }

    // ---- epilogue: quad-reduce l, normalize, store ----
    l0 += __shfl_xor_sync(0xffffffffu, l0, 1);
    l0 += __shfl_xor_sync(0xffffffffu, l0, 2);
    l1 += __shfl_xor_sync(0xffffffffu, l1, 1);
    l1 += __shfl_xor_sync(0xffffffffu, l1, 2);

    if (qi0 < lenq) {
        float inv = 1.f / l0;
        float* op = O + ((long)(q0 + qi0) * HH + h) * DD;
        #pragma unroll
        for (int nt = 0; nt < 8; nt++)
            *(float2*)(op + nt * 8 + 2 * tg) = make_float2(o[nt][0] * inv, o[nt][1] * inv);
    }
    if (qi1 < lenq) {
        float inv = 1.f / l1;
        float* op = O + ((long)(q0 + qi1) * HH + h) * DD;
        #pragma unroll
        for (int nt = 0; nt < 8; nt++)
            *(float2*)(op + nt * 8 + 2 * tg) = make_float2(o[nt][2] * inv, o[nt][3] * inv);
    }
}

extern "C" void kernel_launch(void* const* d_in, const int* in_sizes, int n_in,
                              void* d_out, int out_size)
{
    const float* Q = (const float*)d_in[0];
    const float* K = (const float*)d_in[1];
    const float* V = (const float*)d_in[2];
    const int* cu_q = (const int*)d_in[3];
    const int* cu_k = (const int*)d_in[4];

    int B = in_sizes[3] - 1;
    int T = in_sizes[0] / (HH * DD);

    int max_tiles = (T + BM - 1) / BM + B;
    dim3 grid(max_tiles, HH);
    varlen_attn_mma<<<grid, 128>>>(Q, K, V, cu_q, cu_k, (float*)d_out, B);
}